// round 5
// baseline (speedup 1.0000x reference)
#include <cuda_runtime.h>
#include <cuda_bf16.h>

// ---------------- problem constants ----------------
#define BB     2
#define LLEN   2048
#define DMODEL 1536
#define HH     12
#define FDIM   16
#define DVDIM  128
#define D2     256
#define CH     128
#define NC     16
#define NTOK   4096
#define QKDIM  192
#define QKPAD  256
#define LN_EPS 1e-5f
#define EPS    1e-12f
#define MKS    40                 // MK tile k-stride (bf16)
#define KNS    136                // KN tile n-stride (bf16)
#define ABYT   (128 * MKS * 2)    // 10240 B per MK buffer
#define BBYT   (32 * KNS * 2)     // 8704 B per KN buffer
#define GSTR   (2 * ABYT + 2 * BBYT)  // 37888 gemm/attn_b stage stride
#define KSTR   (4 * BBYT)             // 34816 kvstate stage stride

typedef __nv_bfloat16 bf16;

// ---------------- scratch (device globals) ----------------
__device__ float g_q  [NTOK * QKDIM];
__device__ float g_k  [NTOK * QKDIM];
__device__ float g_S  [(size_t)BB * HH * NC * D2 * DVDIM];
__device__ float g_z  [(size_t)BB * HH * NC * D2];
__device__ float g_den[(size_t)BB * HH * NC * CH];

__device__ __align__(256) bf16 g_xh [(size_t)NTOK * DMODEL];
__device__ __align__(256) bf16 g_xl [(size_t)NTOK * DMODEL];
__device__ __align__(256) bf16 g_wqh[DMODEL * QKPAD];
__device__ __align__(256) bf16 g_wql[DMODEL * QKPAD];
__device__ __align__(256) bf16 g_wkh[DMODEL * QKPAD];
__device__ __align__(256) bf16 g_wkl[DMODEL * QKPAD];
__device__ __align__(256) bf16 g_wvh[DMODEL * DMODEL];
__device__ __align__(256) bf16 g_wvl[DMODEL * DMODEL];
__device__ __align__(256) bf16 g_woh[DMODEL * DMODEL];
__device__ __align__(256) bf16 g_wol[DMODEL * DMODEL];
__device__ __align__(256) bf16 g_vh [(size_t)NTOK * DMODEL];
__device__ __align__(256) bf16 g_vl [(size_t)NTOK * DMODEL];
__device__ __align__(256) bf16 g_Sh [(size_t)BB * HH * NC * D2 * DVDIM];
__device__ __align__(256) bf16 g_Sl [(size_t)BB * HH * NC * D2 * DVDIM];
__device__ __align__(256) bf16 g_Ah [(size_t)BB * HH * NC * CH * CH];
__device__ __align__(256) bf16 g_Al [(size_t)BB * HH * NC * CH * CH];
__device__ __align__(256) bf16 g_ohh[(size_t)NTOK * DMODEL];
__device__ __align__(256) bf16 g_ohl[(size_t)NTOK * DMODEL];

// ---------------- helpers ----------------
__device__ __forceinline__ unsigned sptr(const void* p) {
    return (unsigned)__cvta_generic_to_shared(p);
}
__device__ __forceinline__ void split2(float x, float y, unsigned& h, unsigned& l) {
    __nv_bfloat162 hh = __floats2bfloat162_rn(x, y);
    float rx = x - __low2float(hh);
    float ry = y - __high2float(hh);
    __nv_bfloat162 ll = __floats2bfloat162_rn(rx, ry);
    h = *reinterpret_cast<unsigned*>(&hh);
    l = *reinterpret_cast<unsigned*>(&ll);
}
__device__ __forceinline__ void split8(const float* v, uint4& h, uint4& l) {
    split2(v[0], v[1], h.x, l.x);
    split2(v[2], v[3], h.y, l.y);
    split2(v[4], v[5], h.z, l.z);
    split2(v[6], v[7], h.w, l.w);
}
__device__ __forceinline__ void mma16(float* c, const unsigned* a, const unsigned* b) {
    asm volatile("mma.sync.aligned.m16n8k16.row.col.f32.bf16.bf16.f32 "
        "{%0,%1,%2,%3},{%4,%5,%6,%7},{%8,%9},{%0,%1,%2,%3};"
        : "+f"(c[0]), "+f"(c[1]), "+f"(c[2]), "+f"(c[3])
        : "r"(a[0]), "r"(a[1]), "r"(a[2]), "r"(a[3]), "r"(b[0]), "r"(b[1]));
}
__device__ __forceinline__ void ldsm4(uint4& r, unsigned a) {
    asm volatile("ldmatrix.sync.aligned.m8n8.x4.shared.b16 {%0,%1,%2,%3},[%4];"
        : "=r"(r.x), "=r"(r.y), "=r"(r.z), "=r"(r.w) : "r"(a));
}
__device__ __forceinline__ void ldsm4t(uint4& r, unsigned a) {
    asm volatile("ldmatrix.sync.aligned.m8n8.x4.trans.shared.b16 {%0,%1,%2,%3},[%4];"
        : "=r"(r.x), "=r"(r.y), "=r"(r.z), "=r"(r.w) : "r"(a));
}
__device__ __forceinline__ void cpa16(unsigned dst, const void* src) {
    asm volatile("cp.async.cg.shared.global [%0], [%1], 16;" :: "r"(dst), "l"(src));
}
__device__ __forceinline__ void cp_commit() {
    asm volatile("cp.async.commit_group;");
}
template<int N> __device__ __forceinline__ void cp_wait() {
    asm volatile("cp.async.wait_group %0;" :: "n"(N));
}
__device__ __forceinline__ void tile3(float* acc, const uint4& ah, const uint4& al,
                                      unsigned bh0, unsigned bh1, unsigned bl0, unsigned bl1) {
    unsigned A[4] = {ah.x, ah.y, ah.z, ah.w};
    unsigned L[4] = {al.x, al.y, al.z, al.w};
    unsigned BH[2] = {bh0, bh1}, BL[2] = {bl0, bl1};
    mma16(acc, A, BH);
    mma16(acc, L, BH);
    mma16(acc, A, BL);
}

// One BK=32 stage via ldmatrix. ATR=false: A from MK (no-trans); true: A from KN (.trans).
template<bool ATR>
__device__ __forceinline__ void mma_stage(unsigned fAh, unsigned fAl,
                                          unsigned fBh, unsigned fBl,
                                          float (*acc)[4]) {
    const int aMT = ATR ? 32 : 1280;
    const int aO  = ATR ? 4352 : 32;
#pragma unroll
    for (int o = 0; o < 2; ++o) {
        uint4 ah[4], al[4], bh[2], bl[2];
#pragma unroll
        for (int mt = 0; mt < 4; ++mt) {
            if (ATR) { ldsm4t(ah[mt], fAh + o * aO + mt * aMT); ldsm4t(al[mt], fAl + o * aO + mt * aMT); }
            else     { ldsm4 (ah[mt], fAh + o * aO + mt * aMT); ldsm4 (al[mt], fAl + o * aO + mt * aMT); }
        }
#pragma unroll
        for (int p = 0; p < 2; ++p) {
            ldsm4t(bh[p], fBh + o * 4352 + p * 32);
            ldsm4t(bl[p], fBl + o * 4352 + p * 32);
        }
#pragma unroll
        for (int mt = 0; mt < 4; ++mt)
#pragma unroll
            for (int p = 0; p < 2; ++p) {
                tile3(acc[mt * 4 + 2 * p],     ah[mt], al[mt], bh[p].x, bh[p].y, bl[p].x, bl[p].y);
                tile3(acc[mt * 4 + 2 * p + 1], ah[mt], al[mt], bh[p].z, bh[p].w, bl[p].z, bl[p].w);
            }
    }
}

// ---------------- split kernels ----------------
__global__ __launch_bounds__(256) void split_kernel(const float* __restrict__ s,
                                                    bf16* __restrict__ hi,
                                                    bf16* __restrict__ lo, int n4) {
    const int i = blockIdx.x * 256 + threadIdx.x;
    if (i >= n4) return;
    float4 v = ((const float4*)s)[i];
    unsigned h0, l0, h1, l1;
    split2(v.x, v.y, h0, l0);
    split2(v.z, v.w, h1, l1);
    ((uint2*)hi)[i] = make_uint2(h0, h1);
    ((uint2*)lo)[i] = make_uint2(l0, l1);
}

__global__ __launch_bounds__(256) void split_wqk_kernel(const float* __restrict__ Wq,
                                                        const float* __restrict__ Wk) {
    const int i = blockIdx.x * 256 + threadIdx.x;   // over 1536*64
    const int row = i >> 6, c4 = (i & 63) * 4;
    const float* W = blockIdx.y ? Wk : Wq;
    bf16* hi = blockIdx.y ? g_wkh : g_wqh;
    bf16* lo = blockIdx.y ? g_wkl : g_wql;
    float4 v = make_float4(0.f, 0.f, 0.f, 0.f);
    if (c4 < QKDIM) v = *(const float4*)(W + (size_t)row * QKDIM + c4);
    unsigned h0, l0, h1, l1;
    split2(v.x, v.y, h0, l0);
    split2(v.z, v.w, h1, l1);
    ((uint2*)hi)[i] = make_uint2(h0, h1);
    ((uint2*)lo)[i] = make_uint2(l0, l1);
}

// ---------------- generic async GEMM: C[M,N] = A[M,K] @ B[K,N] ----------
// A,B pre-split bf16 hi/lo. OUT=0: fp32 C (stride Nlog, col<Nlog guard).
// OUT=1: bf16 hi/lo C (stride Nlog).
template<int OUT>
__global__ __launch_bounds__(256) void gemm_async(
    const bf16* __restrict__ Agh, const bf16* __restrict__ Agl,
    const bf16* __restrict__ Bgh, const bf16* __restrict__ Bgl,
    float* __restrict__ Cf, bf16* __restrict__ Chi, bf16* __restrict__ Clo,
    int N, int K, int Nlog)
{
    extern __shared__ char sm[];
    const unsigned smb = sptr(sm);
    const int tid = threadIdx.x, lane = tid & 31, w = tid >> 5;
    const int g = lane >> 2, t = lane & 3;
    const int mbase = (w & 1) * 64, nbase = (w >> 1) * 32;
    const int m0 = blockIdx.y * 128, n0 = blockIdx.x * 128;
    const unsigned offA = ((mbase + (lane & 15)) * MKS + (lane >> 4) * 8) * 2;
    const unsigned offB = ((((lane >> 3) & 1) * 8 + (lane & 7)) * KNS + nbase + ((lane >> 4) & 1) * 8) * 2;

    float acc[16][4];
#pragma unroll
    for (int i = 0; i < 16; ++i) acc[i][0] = acc[i][1] = acc[i][2] = acc[i][3] = 0.f;

    const int NSt = K >> 5;
    auto issue = [&](int st, int k0) {
        const unsigned base = smb + st * GSTR;
#pragma unroll
        for (int u = 0; u < 2; ++u) {
            const int c = tid + 256 * u;
            {
                const int row = c >> 2, seg = (c & 3) * 8;
                const unsigned d = base + (row * MKS + seg) * 2;
                const size_t so = (size_t)(m0 + row) * K + k0 + seg;
                cpa16(d, Agh + so);
                cpa16(d + ABYT, Agl + so);
            }
            {
                const int row = c >> 4, seg = (c & 15) * 8;
                const unsigned d = base + 2 * ABYT + (row * KNS + seg) * 2;
                const size_t so = (size_t)(k0 + row) * N + n0 + seg;
                cpa16(d, Bgh + so);
                cpa16(d + BBYT, Bgl + so);
            }
        }
        cp_commit();
    };
    issue(0, 0);
    issue(1, 32);
    for (int s = 0; s < NSt; ++s) {
        if (s + 2 < NSt) cp_wait<1>(); else cp_wait<0>();
        __syncthreads();
        if (s + 2 < NSt) issue((s + 2) % 3, (s + 2) * 32);
        const unsigned sb = smb + (s % 3) * GSTR;
        mma_stage<false>(sb + offA, sb + ABYT + offA,
                         sb + 2 * ABYT + offB, sb + 2 * ABYT + BBYT + offB, acc);
    }
#pragma unroll
    for (int mt = 0; mt < 4; ++mt) {
        const int r0 = m0 + mbase + mt * 16 + g;
#pragma unroll
        for (int nt = 0; nt < 4; ++nt) {
            const int col = n0 + nbase + nt * 8 + t * 2;
            const float* a4 = acc[mt * 4 + nt];
            if (OUT == 0) {
                if (col < Nlog) {
                    *(float2*)(Cf + (size_t)r0 * Nlog + col)       = make_float2(a4[0], a4[1]);
                    *(float2*)(Cf + (size_t)(r0 + 8) * Nlog + col) = make_float2(a4[2], a4[3]);
                }
            } else {
                unsigned h, l;
                split2(a4[0], a4[1], h, l);
                *(unsigned*)(Chi + (size_t)r0 * Nlog + col) = h;
                *(unsigned*)(Clo + (size_t)r0 * Nlog + col) = l;
                split2(a4[2], a4[3], h, l);
                *(unsigned*)(Chi + (size_t)(r0 + 8) * Nlog + col) = h;
                *(unsigned*)(Clo + (size_t)(r0 + 8) * Nlog + col) = l;
            }
        }
    }
}

// ---------------- LayerNorm over 192 dims, in place ----------------
__global__ __launch_bounds__(256) void ln_kernel(const float* __restrict__ gq,
                                                 const float* __restrict__ bq,
                                                 const float* __restrict__ gk,
                                                 const float* __restrict__ bk) {
    const int warp = (blockIdx.x * blockDim.x + threadIdx.x) >> 5;
    const int lane = threadIdx.x & 31;
    if (warp >= 2 * NTOK) return;
    const bool isq = warp < NTOK;
    float* p = isq ? (g_q + (size_t)warp * QKDIM) : (g_k + (size_t)(warp - NTOK) * QKDIM);
    const float* gg = isq ? gq : gk;
    const float* bb = isq ? bq : bk;
    float x[6]; float s = 0.f, s2 = 0.f;
#pragma unroll
    for (int i = 0; i < 6; ++i) { x[i] = p[lane + 32 * i]; s += x[i]; s2 = fmaf(x[i], x[i], s2); }
#pragma unroll
    for (int o = 16; o > 0; o >>= 1) {
        s += __shfl_xor_sync(0xffffffffu, s, o);
        s2 += __shfl_xor_sync(0xffffffffu, s2, o);
    }
    const float mu = s * (1.f / QKDIM);
    const float var = s2 * (1.f / QKDIM) - mu * mu;
    const float r = rsqrtf(var + LN_EPS);
#pragma unroll
    for (int i = 0; i < 6; ++i) {
        const int c = lane + 32 * i;
        p[c] = (x[i] - mu) * r * gg[c] + bb[c];
    }
}

// ---------------- per-chunk state: S_c = k2_c^T v_c, z_c = sum k2_c ------
__global__ __launch_bounds__(256) void kvstate_async() {
    extern __shared__ char sm[];
    const unsigned smb = sptr(sm);
    float* ksm = (float*)(sm + 3 * KSTR);     // 128*17 fp32
    const int gx = blockIdx.x;
    const int dhalf = gx & 1, rest = gx >> 1;
    const int ch = rest & (NC - 1), bh = rest / NC;
    const int b = bh / HH, h = bh % HH;
    const int d0 = dhalf * 128;
    const int tid = threadIdx.x, lane = tid & 31, w = tid >> 5;
    const int g = lane >> 2, t = lane & 3;
    const int mbase = (w & 1) * 64, nbase = (w >> 1) * 32;
    const int pc = tid >> 4, eg = (tid & 15) * 8;

    const float* kb = g_k + (size_t)(b * LLEN + ch * CH) * QKDIM + h * FDIM;
    const bf16* vh = g_vh + (size_t)(b * LLEN + ch * CH) * DMODEL + h * DVDIM;
    const bf16* vl = g_vl + (size_t)(b * LLEN + ch * CH) * DMODEL + h * DVDIM;

#pragma unroll
    for (int u = 0; u < 2; ++u) {
        const int lin = tid * 2 + u;
        const int r = lin >> 2, c4 = (lin & 3) * 4;
        float4 kv = *(const float4*)(kb + (size_t)r * QKDIM + c4);
        ksm[r * 17 + c4 + 0] = kv.x; ksm[r * 17 + c4 + 1] = kv.y;
        ksm[r * 17 + c4 + 2] = kv.z; ksm[r * 17 + c4 + 3] = kv.w;
    }

    const int iA = (d0 + eg) >> 4, jb = eg & 15;
    const unsigned offA = ((((lane >> 4) & 1) * 8 + (lane & 7)) * KNS + mbase + ((lane >> 3) & 1) * 8) * 2;
    const unsigned offB = ((((lane >> 3) & 1) * 8 + (lane & 7)) * KNS + nbase + ((lane >> 4) & 1) * 8) * 2;

    float acc[16][4];
#pragma unroll
    for (int i = 0; i < 16; ++i) acc[i][0] = acc[i][1] = acc[i][2] = acc[i][3] = 0.f;
    float zacc[8];
#pragma unroll
    for (int e = 0; e < 8; ++e) zacc[e] = 0.f;

    auto issueB = [&](int st, int c0) {
        const unsigned base = smb + st * KSTR + 2 * BBYT;
#pragma unroll
        for (int u = 0; u < 2; ++u) {
            const int c = tid + 256 * u;
            const int row = c >> 4, seg = (c & 15) * 8;
            const unsigned d = base + (row * KNS + seg) * 2;
            const size_t so = (size_t)(c0 + row) * DMODEL + seg;
            cpa16(d, vh + so);
            cpa16(d + BBYT, vl + so);
        }
        cp_commit();
    };
    auto stageA = [&](int st, int c0) {
        bf16* Ah = (bf16*)(sm + st * KSTR);
        bf16* Al = (bf16*)(sm + st * KSTR + BBYT);
        const int ca = c0 + 2 * pc, cb2 = ca + 1;
        float pa[8], pb[8];
        const float kia = ksm[ca * 17 + iA] * 0.25f;
        const float kib = ksm[cb2 * 17 + iA] * 0.25f;
#pragma unroll
        for (int e = 0; e < 8; ++e) {
            pa[e] = kia * ksm[ca * 17 + jb + e];
            pb[e] = kib * ksm[cb2 * 17 + jb + e];
            zacc[e] += pa[e] + pb[e];
        }
        uint4 h4, l4;
        split8(pa, h4, l4);
        *(uint4*)(Ah + (2 * pc) * KNS + eg) = h4;
        *(uint4*)(Al + (2 * pc) * KNS + eg) = l4;
        split8(pb, h4, l4);
        *(uint4*)(Ah + (2 * pc + 1) * KNS + eg) = h4;
        *(uint4*)(Al + (2 * pc + 1) * KNS + eg) = l4;
    };

    issueB(0, 0);
    issueB(1, 32);
    __syncthreads();            // ksm visible
    stageA(0, 0);
    stageA(1, 32);
    for (int s = 0; s < 4; ++s) {
        if (s + 2 < 4) cp_wait<1>(); else cp_wait<0>();
        __syncthreads();
        if (s + 2 < 4) { stageA((s + 2) % 3, (s + 2) * 32); issueB((s + 2) % 3, (s + 2) * 32); }
        const unsigned sb = smb + (s % 3) * KSTR;
        mma_stage<true>(sb + offA, sb + BBYT + offA,
                        sb + 2 * BBYT + offB, sb + 3 * BBYT + offB, acc);
    }

    float* Sout = g_S + (((size_t)bh * NC + ch) * D2 + d0) * DVDIM;
#pragma unroll
    for (int mt = 0; mt < 4; ++mt) {
        const int r0 = mbase + mt * 16 + g;
#pragma unroll
        for (int nt = 0; nt < 4; ++nt) {
            const int col = nbase + nt * 8 + t * 2;
            const float* a4 = acc[mt * 4 + nt];
            *(float2*)(Sout + (size_t)r0 * DVDIM + col)       = make_float2(a4[0], a4[1]);
            *(float2*)(Sout + (size_t)(r0 + 8) * DVDIM + col) = make_float2(a4[2], a4[3]);
        }
    }
    // z reduction: reuse ksm region as zred[16][128]
    __syncthreads();
#pragma unroll
    for (int e = 0; e < 8; ++e) ksm[pc * 128 + eg + e] = zacc[e];
    __syncthreads();
    if (tid < 128) {
        float z = 0.f;
#pragma unroll
        for (int p = 0; p < 16; ++p) z += ksm[p * 128 + tid];
        g_z[((size_t)bh * NC + ch) * D2 + d0 + tid] = z;
    }
}

// ---------------- exclusive prefix over chunks (emits S hi/lo) ----------
__global__ __launch_bounds__(256) void prefix_kernel() {
    const int NS = BB * HH * D2 * DVDIM;
    const int NZ = BB * HH * D2;
    const int idx = blockIdx.x * blockDim.x + threadIdx.x;
    if (idx < NS) {
        const int bh = idx / (D2 * DVDIM);
        const int rem = idx % (D2 * DVDIM);
        const size_t base = (size_t)bh * NC * D2 * DVDIM + rem;
        float run = 0.f;
#pragma unroll
        for (int c = 0; c < NC; ++c) {
            const size_t p = base + (size_t)c * (D2 * DVDIM);
            const float t2 = g_S[p];
            const bf16 hb = __float2bfloat16(run);
            g_Sh[p] = hb;
            g_Sl[p] = __float2bfloat16(run - __bfloat162float(hb));
            run += t2;
        }
    } else if (idx < NS + NZ) {
        const int j = idx - NS;
        const int bh = j / D2, rem = j % D2;
        const size_t base = (size_t)bh * NC * D2 + rem;
        float run = 0.f;
#pragma unroll
        for (int c = 0; c < NC; ++c) {
            const size_t p = base + (size_t)c * D2;
            const float t2 = g_z[p]; g_z[p] = run; run += t2;
        }
    }
}

// ---------------- attention A (fp32 exact): A = mask((q.k)^2/16), den ----
__global__ __launch_bounds__(256) void attn_a_new() {
    __shared__ float qs[128 * 17];
    __shared__ float ksm[128 * 17];
    __shared__ float Zs[256];
    __shared__ float rsum[256];
    const int gx = blockIdx.x;
    const int ch = gx & (NC - 1), bh = gx / NC;
    const int b = bh / HH, h = bh % HH;
    const int tid = threadIdx.x;
    const float* qb = g_q + (size_t)(b * LLEN + ch * CH) * QKDIM + h * FDIM;
    const float* kb = g_k + (size_t)(b * LLEN + ch * CH) * QKDIM + h * FDIM;
#pragma unroll
    for (int u = 0; u < 2; ++u) {
        const int lin = tid * 2 + u;
        const int r = lin >> 2, c4 = (lin & 3) * 4;
        float4 qv = *(const float4*)(qb + (size_t)r * QKDIM + c4);
        qs[r * 17 + c4 + 0] = qv.x; qs[r * 17 + c4 + 1] = qv.y;
        qs[r * 17 + c4 + 2] = qv.z; qs[r * 17 + c4 + 3] = qv.w;
        float4 kv = *(const float4*)(kb + (size_t)r * QKDIM + c4);
        ksm[r * 17 + c4 + 0] = kv.x; ksm[r * 17 + c4 + 1] = kv.y;
        ksm[r * 17 + c4 + 2] = kv.z; ksm[r * 17 + c4 + 3] = kv.w;
    }
    Zs[tid] = g_z[((size_t)bh * NC + ch) * D2 + tid];
    __syncthreads();

    const int r = tid >> 1, cb = (tid & 1) * 64;
    float qr[16];
#pragma unroll
    for (int i = 0; i < 16; ++i) qr[i] = qs[r * 17 + i];
    float rs = 0.f;
    bf16* Abh = g_Ah + (size_t)gx * CH * CH + (size_t)r * CH + cb;
    bf16* Abl = g_Al + (size_t)gx * CH * CH + (size_t)r * CH + cb;
    for (int cc = 0; cc < 64; cc += 4) {
        float ap[4];
#pragma unroll
        for (int e = 0; e < 4; ++e) {
            const int c = cb + cc + e;
            float sd = 0.f;
#pragma unroll
            for (int i = 0; i < 16; ++i) sd = fmaf(qr[i], ksm[c * 17 + i], sd);
            const float a = (c <= r) ? sd * sd * 0.0625f : 0.f;
            ap[e] = a; rs += a;
        }
        unsigned h0, l0, h1, l1;
        split2(ap[0], ap[1], h0, l0);
        split2(ap[2], ap[3], h1, l1);
        *(uint2*)(Abh + cc) = make_uint2(h0, h1);
        *(uint2*)(Abl + cc) = make_uint2(l0, l1);
    }
    rsum[tid] = rs;
    __syncthreads();
    if (tid < 128) {
        float den = 0.f;
#pragma unroll
        for (int i = 0; i < 16; ++i) {
            float y = 0.f;
#pragma unroll
            for (int j = 0; j < 16; ++j) y = fmaf(Zs[i * 16 + j], qs[tid * 17 + j], y);
            den = fmaf(qs[tid * 17 + i], y, den);
        }
        g_den[(size_t)gx * CH + tid] = den * 0.25f + rsum[2 * tid] + rsum[2 * tid + 1];
    }
}

// ---------------- attention B: o = (q2 S + A v) / (den + eps) ----------
__global__ __launch_bounds__(256) void attn_b_async() {
    extern __shared__ char sm[];
    const unsigned smb = sptr(sm);
    float* qsm  = (float*)(sm + 3 * GSTR);          // 128*17 fp32
    float* dens = (float*)(sm + 3 * GSTR + 8704);   // 128 fp32
    const int gx = blockIdx.x;
    const int ch = gx & (NC - 1), bh = gx / NC;
    const int b = bh / HH, h = bh % HH;
    const int tid = threadIdx.x, lane = tid & 31, w = tid >> 5;
    const int g = lane >> 2, t = lane & 3;
    const int mbase = (w & 1) * 64, nbase = (w >> 1) * 32;
    const int arow = tid >> 1, kseg = (tid & 1) * 16;

    const float* qb = g_q + (size_t)(b * LLEN + ch * CH) * QKDIM + h * FDIM;
    const bf16* Shp = g_Sh + ((size_t)bh * NC + ch) * D2 * DVDIM;
    const bf16* Slp = g_Sl + ((size_t)bh * NC + ch) * D2 * DVDIM;
    const bf16* Agh = g_Ah + (size_t)gx * CH * CH;
    const bf16* Agl = g_Al + (size_t)gx * CH * CH;
    const bf16* vh  = g_vh + (size_t)(b * LLEN + ch * CH) * DMODEL + h * DVDIM;
    const bf16* vl  = g_vl + (size_t)(b * LLEN + ch * CH) * DMODEL + h * DVDIM;

    const unsigned offA = ((mbase + (lane & 15)) * MKS + (lane >> 4) * 8) * 2;
    const unsigned offB = ((((lane >> 3) & 1) * 8 + (lane & 7)) * KNS + nbase + ((lane >> 4) & 1) * 8) * 2;

#pragma unroll
    for (int u = 0; u < 2; ++u) {
        const int lin = tid * 2 + u;
        const int r = lin >> 2, c4 = (lin & 3) * 4;
        float4 qv = *(const float4*)(qb + (size_t)r * QKDIM + c4);
        qsm[r * 17 + c4 + 0] = qv.x; qsm[r * 17 + c4 + 1] = qv.y;
        qsm[r * 17 + c4 + 2] = qv.z; qsm[r * 17 + c4 + 3] = qv.w;
    }
    if (tid < CH) dens[tid] = g_den[(size_t)gx * CH + tid];

    float acc[16][4];
#pragma unroll
    for (int i = 0; i < 16; ++i) acc[i][0] = acc[i][1] = acc[i][2] = acc[i][3] = 0.f;

    // phase 1: q2 (on the fly) @ S, K = 256
    auto issueB1 = [&](int st, int d1) {
        const unsigned base = smb + st * GSTR + 2 * ABYT;
#pragma unroll
        for (int u = 0; u < 2; ++u) {
            const int c = tid + 256 * u;
            const int row = c >> 4, seg = (c & 15) * 8;
            const unsigned d = base + (row * KNS + seg) * 2;
            const size_t so = (size_t)(d1 + row) * DVDIM + seg;
            cpa16(d, Shp + so);
            cpa16(d + BBYT, Slp + so);
        }
        cp_commit();
    };
    auto stageA1 = [&](int st, int sidx) {
        bf16* Ah = (bf16*)(sm + st * GSTR);
        bf16* Al = (bf16*)(sm + st * GSTR + ABYT);
        const int db = sidx * 32 + kseg;
        const float qi = qsm[arow * 17 + (db >> 4)] * 0.25f;
        float p[16];
#pragma unroll
        for (int j = 0; j < 16; ++j) p[j] = qi * qsm[arow * 17 + j];
        uint4 h4, l4;
        split8(p, h4, l4);
        *(uint4*)(Ah + arow * MKS + kseg) = h4;
        *(uint4*)(Al + arow * MKS + kseg) = l4;
        split8(p + 8, h4, l4);
        *(uint4*)(Ah + arow * MKS + kseg + 8) = h4;
        *(uint4*)(Al + arow * MKS + kseg + 8) = l4;
    };
    issueB1(0, 0);
    issueB1(1, 32);
    __syncthreads();            // qsm visible
    stageA1(0, 0);
    stageA1(1, 1);
    for (int s = 0; s < 8; ++s) {
        if (s + 2 < 8) cp_wait<1>(); else cp_wait<0>();
        __syncthreads();
        if (s + 2 < 8) { stageA1((s + 2) % 3, s + 2); issueB1((s + 2) % 3, (s + 2) * 32); }
        const unsigned sb = smb + (s % 3) * GSTR;
        mma_stage<false>(sb + offA, sb + ABYT + offA,
                         sb + 2 * ABYT + offB, sb + 2 * ABYT + BBYT + offB, acc);
    }
    __syncthreads();            // phase boundary

    // phase 2: A @ v, K = 128
    auto issueAB2 = [&](int st, int c0) {
        const unsigned base = smb + st * GSTR;
#pragma unroll
        for (int u = 0; u < 2; ++u) {
            const int c = tid + 256 * u;
            {
                const int row = c >> 2, seg = (c & 3) * 8;
                const unsigned d = base + (row * MKS + seg) * 2;
                const size_t so = (size_t)row * CH + c0 + seg;
                cpa16(d, Agh + so);
                cpa16(d + ABYT, Agl + so);
            }
            {
                const int row = c >> 4, seg = (c & 15) * 8;
                const unsigned d = base + 2 * ABYT + (row * KNS + seg) * 2;
                const size_t so = (size_t)(c0 + row) * DMODEL + seg;
                cpa16(d, vh + so);
                cpa16(d + BBYT, vl + so);
            }
        }
        cp_commit();
    };
    issueAB2(0, 0);
    issueAB2(1, 32);
    for (int s = 0; s < 4; ++s) {
        if (s + 2 < 4) cp_wait<1>(); else cp_wait<0>();
        __syncthreads();
        if (s + 2 < 4) issueAB2((s + 2) % 3, (s + 2) * 32);
        const unsigned sb = smb + (s % 3) * GSTR;
        mma_stage<false>(sb + offA, sb + ABYT + offA,
                         sb + 2 * ABYT + offB, sb + 2 * ABYT + BBYT + offB, acc);
    }

    const size_t obase = (size_t)(b * LLEN + ch * CH) * DMODEL + h * DVDIM;
#pragma unroll
    for (int mt = 0; mt < 4; ++mt) {
        const int r0 = mbase + mt * 16 + g;
        const float inv0 = 1.f / (dens[r0] + EPS);
        const float inv1 = 1.f / (dens[r0 + 8] + EPS);
#pragma unroll
        for (int nt = 0; nt < 4; ++nt) {
            const int col = nbase + nt * 8 + t * 2;
            const float* a4 = acc[mt * 4 + nt];
            unsigned hh, ll;
            split2(a4[0] * inv0, a4[1] * inv0, hh, ll);
            *(unsigned*)(g_ohh + obase + (size_t)r0 * DMODEL + col) = hh;
            *(unsigned*)(g_ohl + obase + (size_t)r0 * DMODEL + col) = ll;
            split2(a4[2] * inv1, a4[3] * inv1, hh, ll);
            *(unsigned*)(g_ohh + obase + (size_t)(r0 + 8) * DMODEL + col) = hh;
            *(unsigned*)(g_ohl + obase + (size_t)(r0 + 8) * DMODEL + col) = ll;
        }
    }
}

// ---------------- host pipeline ----------------
extern "C" void kernel_launch(void* const* d_in, const int* in_sizes, int n_in,
                              void* d_out, int out_size) {
    (void)in_sizes; (void)n_in; (void)out_size;
    const float* x   = (const float*)d_in[0];
    const float* Wq  = (const float*)d_in[1];
    const float* Wk  = (const float*)d_in[2];
    const float* Wv  = (const float*)d_in[3];
    const float* Wo  = (const float*)d_in[4];
    const float* lqg = (const float*)d_in[5];
    const float* lqb = (const float*)d_in[6];
    const float* lkg = (const float*)d_in[7];
    const float* lkb = (const float*)d_in[8];
    float* out = (float*)d_out;

    const int GEMM_SM = 3 * GSTR;               // 113664
    const int KV_SM   = 3 * KSTR + 8704;        // 113152
    const int AB_SM   = 3 * GSTR + 8704 + 512;  // 122880
    cudaFuncSetAttribute(gemm_async<0>, cudaFuncAttributeMaxDynamicSharedMemorySize, GEMM_SM);
    cudaFuncSetAttribute(gemm_async<1>, cudaFuncAttributeMaxDynamicSharedMemorySize, GEMM_SM);
    cudaFuncSetAttribute(kvstate_async, cudaFuncAttributeMaxDynamicSharedMemorySize, KV_SM);
    cudaFuncSetAttribute(attn_b_async,  cudaFuncAttributeMaxDynamicSharedMemorySize, AB_SM);

    bf16 *xh, *xl, *wqh, *wql, *wkh, *wkl, *wvh, *wvl, *woh, *wol;
    bf16 *vhp, *vlp, *ohh, *ohl;
    float *qp, *kp;
    cudaGetSymbolAddress((void**)&xh,  g_xh);  cudaGetSymbolAddress((void**)&xl,  g_xl);
    cudaGetSymbolAddress((void**)&wqh, g_wqh); cudaGetSymbolAddress((void**)&wql, g_wql);
    cudaGetSymbolAddress((void**)&wkh, g_wkh); cudaGetSymbolAddress((void**)&wkl, g_wkl);
    cudaGetSymbolAddress((void**)&wvh, g_wvh); cudaGetSymbolAddress((void**)&wvl, g_wvl);
    cudaGetSymbolAddress((void**)&woh, g_woh); cudaGetSymbolAddress((void**)&wol, g_wol);
    cudaGetSymbolAddress((void**)&vhp, g_vh);  cudaGetSymbolAddress((void**)&vlp, g_vl);
    cudaGetSymbolAddress((void**)&ohh, g_ohh); cudaGetSymbolAddress((void**)&ohl, g_ohl);
    cudaGetSymbolAddress((void**)&qp,  g_q);   cudaGetSymbolAddress((void**)&kp,  g_k);

    // splits
    split_kernel<<<(NTOK * DMODEL / 4 + 255) / 256, 256>>>(x, xh, xl, NTOK * DMODEL / 4);
    split_wqk_kernel<<<dim3(DMODEL * (QKPAD / 4) / 256, 2), 256>>>(Wq, Wk);
    split_kernel<<<(DMODEL * DMODEL / 4 + 255) / 256, 256>>>(Wv, wvh, wvl, DMODEL * DMODEL / 4);
    split_kernel<<<(DMODEL * DMODEL / 4 + 255) / 256, 256>>>(Wo, woh, wol, DMODEL * DMODEL / 4);

    // projections
    gemm_async<0><<<dim3(2, 32), 256, GEMM_SM>>>(xh, xl, wqh, wql, qp, nullptr, nullptr, QKPAD, DMODEL, QKDIM);
    gemm_async<0><<<dim3(2, 32), 256, GEMM_SM>>>(xh, xl, wkh, wkl, kp, nullptr, nullptr, QKPAD, DMODEL, QKDIM);
    gemm_async<1><<<dim3(12, 32), 256, GEMM_SM>>>(xh, xl, wvh, wvl, nullptr, vhp, vlp, DMODEL, DMODEL, DMODEL);
    ln_kernel<<<(2 * NTOK) / 8, 256>>>(lqg, lqb, lkg, lkb);
    // chunked linear attention
    kvstate_async<<<BB * HH * NC * 2, 256, KV_SM>>>();
    {
        const int total = BB * HH * D2 * DVDIM + BB * HH * D2;
        prefix_kernel<<<(total + 255) / 256, 256>>>();
    }
    attn_a_new<<<BB * HH * NC, 256>>>();
    attn_b_async<<<BB * HH * NC, 256, AB_SM>>>();
    // output projection
    gemm_async<0><<<dim3(12, 32), 256, GEMM_SM>>>(ohh, ohl, woh, wol, out, nullptr, nullptr, DMODEL, DMODEL, DMODEL);
}

// round 6
// speedup vs baseline: 1.1737x; 1.1737x over previous
#include <cuda_runtime.h>
#include <cuda_bf16.h>

// ---------------- problem constants ----------------
#define BB     2
#define LLEN   2048
#define DMODEL 1536
#define HH     12
#define FDIM   16
#define DVDIM  128
#define D2     256
#define CH     128
#define NC     16
#define NTOK   4096
#define QKDIM  192
#define LN_EPS 1e-5f
#define EPS    1e-12f
#define MKS    40                 // MK tile k-stride (bf16)
#define KNS    136                // KN tile n-stride (bf16)
#define ABYT   (128 * MKS * 2)    // 10240 B per MK buffer
#define BBYT   (32 * KNS * 2)     // 8704 B per KN buffer
#define GSTR   (2 * ABYT + 2 * BBYT)  // 37888: gemm/attn_b buffer stride
#define KSTR   (4 * BBYT)             // 34816: kvstate buffer stride

typedef __nv_bfloat16 bf16;

// ---------------- scratch (device globals) ----------------
__device__ float g_q  [NTOK * QKDIM];
__device__ float g_k  [NTOK * QKDIM];
__device__ float g_v  [(size_t)NTOK * DMODEL];
__device__ float g_S  [(size_t)BB * HH * NC * D2 * DVDIM];
__device__ float g_z  [(size_t)BB * HH * NC * D2];
__device__ float g_A  [(size_t)BB * HH * NC * CH * CH];
__device__ float g_den[(size_t)BB * HH * NC * CH];
__device__ float g_oh [(size_t)NTOK * DMODEL];

// ---------------- helpers ----------------
__device__ __forceinline__ unsigned sptr(const void* p) {
    return (unsigned)__cvta_generic_to_shared(p);
}
__device__ __forceinline__ void split2(float x, float y, unsigned& h, unsigned& l) {
    __nv_bfloat162 hh = __floats2bfloat162_rn(x, y);
    float rx = x - __low2float(hh);
    float ry = y - __high2float(hh);
    __nv_bfloat162 ll = __floats2bfloat162_rn(rx, ry);
    h = *reinterpret_cast<unsigned*>(&hh);
    l = *reinterpret_cast<unsigned*>(&ll);
}
__device__ __forceinline__ void split8(const float* v, uint4& h, uint4& l) {
    split2(v[0], v[1], h.x, l.x);
    split2(v[2], v[3], h.y, l.y);
    split2(v[4], v[5], h.z, l.z);
    split2(v[6], v[7], h.w, l.w);
}
__device__ __forceinline__ void mma16(float* c, const unsigned* a, const unsigned* b) {
    asm volatile("mma.sync.aligned.m16n8k16.row.col.f32.bf16.bf16.f32 "
        "{%0,%1,%2,%3},{%4,%5,%6,%7},{%8,%9},{%0,%1,%2,%3};"
        : "+f"(c[0]), "+f"(c[1]), "+f"(c[2]), "+f"(c[3])
        : "r"(a[0]), "r"(a[1]), "r"(a[2]), "r"(a[3]), "r"(b[0]), "r"(b[1]));
}
__device__ __forceinline__ void ldsm4(uint4& r, unsigned a) {
    asm volatile("ldmatrix.sync.aligned.m8n8.x4.shared.b16 {%0,%1,%2,%3},[%4];"
        : "=r"(r.x), "=r"(r.y), "=r"(r.z), "=r"(r.w) : "r"(a));
}
__device__ __forceinline__ void ldsm4t(uint4& r, unsigned a) {
    asm volatile("ldmatrix.sync.aligned.m8n8.x4.trans.shared.b16 {%0,%1,%2,%3},[%4];"
        : "=r"(r.x), "=r"(r.y), "=r"(r.z), "=r"(r.w) : "r"(a));
}
__device__ __forceinline__ void tile3(float* acc, const uint4& ah, const uint4& al,
                                      unsigned bh0, unsigned bh1, unsigned bl0, unsigned bl1) {
    unsigned A[4] = {ah.x, ah.y, ah.z, ah.w};
    unsigned L[4] = {al.x, al.y, al.z, al.w};
    unsigned BH[2] = {bh0, bh1}, BL[2] = {bl0, bl1};
    mma16(acc, A, BH);
    mma16(acc, L, BH);
    mma16(acc, A, BL);
}

// One BK=32 stage via ldmatrix. ATR=false: A from MK (no-trans); true: A from KN (.trans).
template<bool ATR>
__device__ __forceinline__ void mma_stage(unsigned fAh, unsigned fAl,
                                          unsigned fBh, unsigned fBl,
                                          float (*acc)[4]) {
    const int aMT = ATR ? 32 : 1280;
    const int aO  = ATR ? 4352 : 32;
#pragma unroll
    for (int o = 0; o < 2; ++o) {
        uint4 ah[4], al[4], bh[2], bl[2];
#pragma unroll
        for (int mt = 0; mt < 4; ++mt) {
            if (ATR) { ldsm4t(ah[mt], fAh + o * aO + mt * aMT); ldsm4t(al[mt], fAl + o * aO + mt * aMT); }
            else     { ldsm4 (ah[mt], fAh + o * aO + mt * aMT); ldsm4 (al[mt], fAl + o * aO + mt * aMT); }
        }
#pragma unroll
        for (int p = 0; p < 2; ++p) {
            ldsm4t(bh[p], fBh + o * 4352 + p * 32);
            ldsm4t(bl[p], fBl + o * 4352 + p * 32);
        }
#pragma unroll
        for (int mt = 0; mt < 4; ++mt)
#pragma unroll
            for (int p = 0; p < 2; ++p) {
                tile3(acc[mt * 4 + 2 * p],     ah[mt], al[mt], bh[p].x, bh[p].y, bl[p].x, bl[p].y);
                tile3(acc[mt * 4 + 2 * p + 1], ah[mt], al[mt], bh[p].z, bh[p].w, bl[p].z, bl[p].w);
            }
    }
}

// ---------------- generic projection GEMM core (double-buffered) --------
__device__ __forceinline__ void gemm_core(const float* __restrict__ A,
                                          const float* __restrict__ B,
                                          float* __restrict__ C,
                                          int N, int K, int m0, int n0, char* sm) {
    const unsigned smb = sptr(sm);
    const int tid = threadIdx.x, lane = tid & 31, w = tid >> 5;
    const int g = lane >> 2, t = lane & 3;
    const int mbase = (w & 1) * 64, nbase = (w >> 1) * 32;
    const int arow = tid >> 1, kseg = (tid & 1) * 16;
    const int krow = tid >> 3, nseg = (tid & 7) * 16;
    const bool bval = (n0 + nseg) < N;
    const unsigned offA = ((mbase + (lane & 15)) * MKS + (lane >> 4) * 8) * 2;
    const unsigned offB = ((((lane >> 3) & 1) * 8 + (lane & 7)) * KNS + nbase + ((lane >> 4) & 1) * 8) * 2;

    float acc[16][4];
#pragma unroll
    for (int i = 0; i < 16; ++i) acc[i][0] = acc[i][1] = acc[i][2] = acc[i][3] = 0.f;

    float4 ra[4], rb[4];
    auto loadRegs = [&](int k0) {
#pragma unroll
        for (int i = 0; i < 4; ++i) {
            ra[i] = *(const float4*)(A + (size_t)(m0 + arow) * K + k0 + kseg + 4 * i);
            rb[i] = bval ? *(const float4*)(B + (size_t)(k0 + krow) * N + n0 + nseg + 4 * i)
                         : make_float4(0.f, 0.f, 0.f, 0.f);
        }
    };
    auto storeStage = [&](int bsel) {
        bf16* Ah = (bf16*)(sm + bsel * GSTR);
        bf16* Al = (bf16*)(sm + bsel * GSTR + ABYT);
        bf16* Bh = (bf16*)(sm + bsel * GSTR + 2 * ABYT);
        bf16* Bl = (bf16*)(sm + bsel * GSTR + 2 * ABYT + BBYT);
        uint4 h4, l4;
        split8((const float*)&ra[0], h4, l4);
        *(uint4*)(Ah + arow * MKS + kseg) = h4;     *(uint4*)(Al + arow * MKS + kseg) = l4;
        split8((const float*)&ra[2], h4, l4);
        *(uint4*)(Ah + arow * MKS + kseg + 8) = h4; *(uint4*)(Al + arow * MKS + kseg + 8) = l4;
        split8((const float*)&rb[0], h4, l4);
        *(uint4*)(Bh + krow * KNS + nseg) = h4;     *(uint4*)(Bl + krow * KNS + nseg) = l4;
        split8((const float*)&rb[2], h4, l4);
        *(uint4*)(Bh + krow * KNS + nseg + 8) = h4; *(uint4*)(Bl + krow * KNS + nseg + 8) = l4;
    };

    const int NSt = K >> 5;
    loadRegs(0);
    storeStage(0);
    loadRegs(32);
    __syncthreads();
    for (int s = 0; s < NSt; ++s) {
        const unsigned sb = smb + (s & 1) * GSTR;
        mma_stage<false>(sb + offA, sb + ABYT + offA,
                         sb + 2 * ABYT + offB, sb + 2 * ABYT + BBYT + offB, acc);
        if (s + 1 < NSt) {
            storeStage((s + 1) & 1);
            if (s + 2 < NSt) loadRegs((s + 2) * 32);
        }
        __syncthreads();
    }
#pragma unroll
    for (int mt = 0; mt < 4; ++mt) {
        const int r0 = m0 + mbase + mt * 16 + g;
#pragma unroll
        for (int nt = 0; nt < 4; ++nt) {
            const int col = n0 + nbase + nt * 8 + t * 2;
            if (col < N) {
                const float* a4 = acc[mt * 4 + nt];
                *(float2*)(C + (size_t)r0 * N + col)       = make_float2(a4[0], a4[1]);
                *(float2*)(C + (size_t)(r0 + 8) * N + col) = make_float2(a4[2], a4[3]);
            }
        }
    }
}

__global__ __launch_bounds__(256) void projqk_kernel(const float* __restrict__ x,
                                                     const float* __restrict__ Wq,
                                                     const float* __restrict__ Wk) {
    extern __shared__ char sm[];
    const float* B = blockIdx.z ? Wk : Wq;
    float* C = blockIdx.z ? (float*)g_k : (float*)g_q;
    gemm_core(x, B, C, QKDIM, DMODEL, blockIdx.y * 128, blockIdx.x * 128, sm);
}

__global__ __launch_bounds__(256) void proj_kernel(const float* __restrict__ A,
                                                   const float* __restrict__ B,
                                                   float* __restrict__ C, int N, int K) {
    extern __shared__ char sm[];
    gemm_core(A, B, C, N, K, blockIdx.y * 128, blockIdx.x * 128, sm);
}

// ---------------- LayerNorm over 192 dims, in place ----------------
__global__ __launch_bounds__(256) void ln_kernel(const float* __restrict__ gq,
                                                 const float* __restrict__ bq,
                                                 const float* __restrict__ gk,
                                                 const float* __restrict__ bk) {
    const int warp = (blockIdx.x * blockDim.x + threadIdx.x) >> 5;
    const int lane = threadIdx.x & 31;
    if (warp >= 2 * NTOK) return;
    const bool isq = warp < NTOK;
    float* p = isq ? (g_q + (size_t)warp * QKDIM) : (g_k + (size_t)(warp - NTOK) * QKDIM);
    const float* gg = isq ? gq : gk;
    const float* bb = isq ? bq : bk;
    float x[6]; float s = 0.f, s2 = 0.f;
#pragma unroll
    for (int i = 0; i < 6; ++i) { x[i] = p[lane + 32 * i]; s += x[i]; s2 = fmaf(x[i], x[i], s2); }
#pragma unroll
    for (int o = 16; o > 0; o >>= 1) {
        s += __shfl_xor_sync(0xffffffffu, s, o);
        s2 += __shfl_xor_sync(0xffffffffu, s2, o);
    }
    const float mu = s * (1.f / QKDIM);
    const float var = s2 * (1.f / QKDIM) - mu * mu;
    const float r = rsqrtf(var + LN_EPS);
#pragma unroll
    for (int i = 0; i < 6; ++i) {
        const int c = lane + 32 * i;
        p[c] = (x[i] - mu) * r * gg[c] + bb[c];
    }
}

// ---------------- per-chunk state: S_c = k2_c^T v_c, z_c = sum k2_c ------
__global__ __launch_bounds__(256) void kvstate_db() {
    extern __shared__ char sm[];
    const unsigned smb = sptr(sm);
    float* ksm = (float*)(sm + 2 * KSTR);     // 128*17 fp32; reused as zred
    const int gx = blockIdx.x;
    const int dhalf = gx & 1, rest = gx >> 1;
    const int ch = rest & (NC - 1), bh = rest / NC;
    const int b = bh / HH, h = bh % HH;
    const int d0 = dhalf * 128;
    const int tid = threadIdx.x, lane = tid & 31, w = tid >> 5;
    const int g = lane >> 2, t = lane & 3;
    const int mbase = (w & 1) * 64, nbase = (w >> 1) * 32;
    const int pc = tid >> 4, eg = (tid & 15) * 8;

    const float* kb = g_k + (size_t)(b * LLEN + ch * CH) * QKDIM + h * FDIM;
    const float* vb = g_v + (size_t)(b * LLEN + ch * CH) * DMODEL + h * DVDIM;

#pragma unroll
    for (int u = 0; u < 2; ++u) {
        const int lin = tid * 2 + u;
        const int r = lin >> 2, c4 = (lin & 3) * 4;
        float4 kv = *(const float4*)(kb + (size_t)r * QKDIM + c4);
        ksm[r * 17 + c4 + 0] = kv.x; ksm[r * 17 + c4 + 1] = kv.y;
        ksm[r * 17 + c4 + 2] = kv.z; ksm[r * 17 + c4 + 3] = kv.w;
    }

    const int iA = (d0 + eg) >> 4, jb = eg & 15;
    const unsigned offA = ((((lane >> 4) & 1) * 8 + (lane & 7)) * KNS + mbase + ((lane >> 3) & 1) * 8) * 2;
    const unsigned offB = ((((lane >> 3) & 1) * 8 + (lane & 7)) * KNS + nbase + ((lane >> 4) & 1) * 8) * 2;

    float acc[16][4];
#pragma unroll
    for (int i = 0; i < 16; ++i) acc[i][0] = acc[i][1] = acc[i][2] = acc[i][3] = 0.f;
    float zacc[8];
#pragma unroll
    for (int e = 0; e < 8; ++e) zacc[e] = 0.f;

    float vA[8], vB[8];
    auto loadV = [&](int c0) {
        const float* r0p = vb + (size_t)(c0 + 2 * pc) * DMODEL + eg;
        const float* r1p = vb + (size_t)(c0 + 2 * pc + 1) * DMODEL + eg;
        *(float4*)&vA[0] = *(const float4*)r0p; *(float4*)&vA[4] = *(const float4*)(r0p + 4);
        *(float4*)&vB[0] = *(const float4*)r1p; *(float4*)&vB[4] = *(const float4*)(r1p + 4);
    };
    auto stage = [&](int bsel, int c0) {
        bf16* Ah = (bf16*)(sm + bsel * KSTR);
        bf16* Al = (bf16*)(sm + bsel * KSTR + BBYT);
        bf16* Bh = (bf16*)(sm + bsel * KSTR + 2 * BBYT);
        bf16* Bl = (bf16*)(sm + bsel * KSTR + 3 * BBYT);
        const int ca = c0 + 2 * pc, cb2 = ca + 1;
        float pa[8], pb[8];
        const float kia = ksm[ca * 17 + iA] * 0.25f;
        const float kib = ksm[cb2 * 17 + iA] * 0.25f;
#pragma unroll
        for (int e = 0; e < 8; ++e) {
            pa[e] = kia * ksm[ca * 17 + jb + e];
            pb[e] = kib * ksm[cb2 * 17 + jb + e];
            zacc[e] += pa[e] + pb[e];
        }
        uint4 h4, l4;
        split8(pa, h4, l4);
        *(uint4*)(Ah + (2 * pc) * KNS + eg) = h4;     *(uint4*)(Al + (2 * pc) * KNS + eg) = l4;
        split8(pb, h4, l4);
        *(uint4*)(Ah + (2 * pc + 1) * KNS + eg) = h4; *(uint4*)(Al + (2 * pc + 1) * KNS + eg) = l4;
        split8(vA, h4, l4);
        *(uint4*)(Bh + (2 * pc) * KNS + eg) = h4;     *(uint4*)(Bl + (2 * pc) * KNS + eg) = l4;
        split8(vB, h4, l4);
        *(uint4*)(Bh + (2 * pc + 1) * KNS + eg) = h4; *(uint4*)(Bl + (2 * pc + 1) * KNS + eg) = l4;
    };

    loadV(0);
    __syncthreads();            // ksm visible
    stage(0, 0);
    loadV(32);
    __syncthreads();
    for (int s = 0; s < 4; ++s) {
        const unsigned sb = smb + (s & 1) * KSTR;
        mma_stage<true>(sb + offA, sb + BBYT + offA,
                        sb + 2 * BBYT + offB, sb + 3 * BBYT + offB, acc);
        if (s + 1 < 4) {
            stage((s + 1) & 1, (s + 1) * 32);
            if (s + 2 < 4) loadV((s + 2) * 32);
        }
        __syncthreads();
    }

    float* Sout = g_S + (((size_t)bh * NC + ch) * D2 + d0) * DVDIM;
#pragma unroll
    for (int mt = 0; mt < 4; ++mt) {
        const int r0 = mbase + mt * 16 + g;
#pragma unroll
        for (int nt = 0; nt < 4; ++nt) {
            const int col = nbase + nt * 8 + t * 2;
            const float* a4 = acc[mt * 4 + nt];
            *(float2*)(Sout + (size_t)r0 * DVDIM + col)       = make_float2(a4[0], a4[1]);
            *(float2*)(Sout + (size_t)(r0 + 8) * DVDIM + col) = make_float2(a4[2], a4[3]);
        }
    }
    // z reduction: reuse ksm region as zred[16][128]
#pragma unroll
    for (int e = 0; e < 8; ++e) ksm[pc * 128 + eg + e] = zacc[e];
    __syncthreads();
    if (tid < 128) {
        float z = 0.f;
#pragma unroll
        for (int p = 0; p < 16; ++p) z += ksm[p * 128 + tid];
        g_z[((size_t)bh * NC + ch) * D2 + d0 + tid] = z;
    }
}

// ---------------- exclusive prefix over chunks ----------------
__global__ __launch_bounds__(256) void prefix_kernel() {
    const int NS = BB * HH * D2 * DVDIM;
    const int NZ = BB * HH * D2;
    const int idx = blockIdx.x * blockDim.x + threadIdx.x;
    if (idx < NS) {
        const int bh = idx / (D2 * DVDIM);
        const int rem = idx % (D2 * DVDIM);
        const size_t base = (size_t)bh * NC * D2 * DVDIM + rem;
        float run = 0.f;
#pragma unroll
        for (int c = 0; c < NC; ++c) {
            const size_t p = base + (size_t)c * (D2 * DVDIM);
            const float t2 = g_S[p]; g_S[p] = run; run += t2;
        }
    } else if (idx < NS + NZ) {
        const int j = idx - NS;
        const int bh = j / D2, rem = j % D2;
        const size_t base = (size_t)bh * NC * D2 + rem;
        float run = 0.f;
#pragma unroll
        for (int c = 0; c < NC; ++c) {
            const size_t p = base + (size_t)c * D2;
            const float t2 = g_z[p]; g_z[p] = run; run += t2;
        }
    }
}

// ---------------- attention A (fp32 exact): A = mask((q.k)^2/16), den ----
__global__ __launch_bounds__(256) void attn_a_new() {
    __shared__ float qs[128 * 17];
    __shared__ float ksm[128 * 17];
    __shared__ float Zs[256];
    __shared__ float rsum[256];
    const int gx = blockIdx.x;
    const int ch = gx & (NC - 1), bh = gx / NC;
    const int b = bh / HH, h = bh % HH;
    const int tid = threadIdx.x;
    const float* qb = g_q + (size_t)(b * LLEN + ch * CH) * QKDIM + h * FDIM;
    const float* kb = g_k + (size_t)(b * LLEN + ch * CH) * QKDIM + h * FDIM;
#pragma unroll
    for (int u = 0; u < 2; ++u) {
        const int lin = tid * 2 + u;
        const int r = lin >> 2, c4 = (lin & 3) * 4;
        float4 qv = *(const float4*)(qb + (size_t)r * QKDIM + c4);
        qs[r * 17 + c4 + 0] = qv.x; qs[r * 17 + c4 + 1] = qv.y;
        qs[r * 17 + c4 + 2] = qv.z; qs[r * 17 + c4 + 3] = qv.w;
        float4 kv = *(const float4*)(kb + (size_t)r * QKDIM + c4);
        ksm[r * 17 + c4 + 0] = kv.x; ksm[r * 17 + c4 + 1] = kv.y;
        ksm[r * 17 + c4 + 2] = kv.z; ksm[r * 17 + c4 + 3] = kv.w;
    }
    Zs[tid] = g_z[((size_t)bh * NC + ch) * D2 + tid];
    __syncthreads();

    const int r = tid >> 1, cb = (tid & 1) * 64;
    float qr[16];
#pragma unroll
    for (int i = 0; i < 16; ++i) qr[i] = qs[r * 17 + i];
    float rs = 0.f;
    float* Ab = g_A + (size_t)gx * CH * CH + (size_t)r * CH + cb;
    for (int cc = 0; cc < 64; cc += 4) {
        float4 av;
        float* ap = (float*)&av;
#pragma unroll
        for (int e = 0; e < 4; ++e) {
            const int c = cb + cc + e;
            float sd = 0.f;
#pragma unroll
            for (int i = 0; i < 16; ++i) sd = fmaf(qr[i], ksm[c * 17 + i], sd);
            const float a = (c <= r) ? sd * sd * 0.0625f : 0.f;
            ap[e] = a; rs += a;
        }
        *(float4*)(Ab + cc) = av;
    }
    rsum[tid] = rs;
    __syncthreads();
    if (tid < 128) {
        float den = 0.f;
#pragma unroll
        for (int i = 0; i < 16; ++i) {
            float y = 0.f;
#pragma unroll
            for (int j = 0; j < 16; ++j) y = fmaf(Zs[i * 16 + j], qs[tid * 17 + j], y);
            den = fmaf(qs[tid * 17 + i], y, den);
        }
        g_den[(size_t)gx * CH + tid] = den * 0.25f + rsum[2 * tid] + rsum[2 * tid + 1];
    }
}

// ---------------- attention B: o = (q2 S + A v) / (den + eps) ----------
// Unified 12-stage double-buffered pipeline (8 stages q2@S, 4 stages A@v).
__global__ __launch_bounds__(256) void attn_b_db() {
    extern __shared__ char sm[];
    const unsigned smb = sptr(sm);
    float* qsm  = (float*)(sm + 2 * GSTR);          // 128*17 fp32
    float* dens = (float*)(sm + 2 * GSTR + 8704);   // 128 fp32
    const int gx = blockIdx.x;
    const int ch = gx & (NC - 1), bh = gx / NC;
    const int b = bh / HH, h = bh % HH;
    const int tid = threadIdx.x, lane = tid & 31, w = tid >> 5;
    const int g = lane >> 2, t = lane & 3;
    const int mbase = (w & 1) * 64, nbase = (w >> 1) * 32;
    const int arow = tid >> 1, kseg = (tid & 1) * 16;
    const int pkr = tid >> 4, bn = (tid & 15) * 8;

    const float* qb  = g_q + (size_t)(b * LLEN + ch * CH) * QKDIM + h * FDIM;
    const float* Sb  = g_S + ((size_t)bh * NC + ch) * D2 * DVDIM;
    const float* Abp = g_A + (size_t)gx * CH * CH;
    const float* vb  = g_v + (size_t)(b * LLEN + ch * CH) * DMODEL + h * DVDIM;

    const unsigned offA = ((mbase + (lane & 15)) * MKS + (lane >> 4) * 8) * 2;
    const unsigned offB = ((((lane >> 3) & 1) * 8 + (lane & 7)) * KNS + nbase + ((lane >> 4) & 1) * 8) * 2;

#pragma unroll
    for (int u = 0; u < 2; ++u) {
        const int lin = tid * 2 + u;
        const int r = lin >> 2, c4 = (lin & 3) * 4;
        float4 qv = *(const float4*)(qb + (size_t)r * QKDIM + c4);
        qsm[r * 17 + c4 + 0] = qv.x; qsm[r * 17 + c4 + 1] = qv.y;
        qsm[r * 17 + c4 + 2] = qv.z; qsm[r * 17 + c4 + 3] = qv.w;
    }
    if (tid < CH) dens[tid] = g_den[(size_t)gx * CH + tid];

    float acc[16][4];
#pragma unroll
    for (int i = 0; i < 16; ++i) acc[i][0] = acc[i][1] = acc[i][2] = acc[i][3] = 0.f;

    float bA[8], bB[8];
    float4 raf[4];
    auto loadB = [&](int s) {
        const float* r0p;
        const float* r1p;
        if (s < 8) {
            r0p = Sb + (size_t)(s * 32 + 2 * pkr) * DVDIM + bn;
            r1p = Sb + (size_t)(s * 32 + 2 * pkr + 1) * DVDIM + bn;
        } else {
            r0p = vb + (size_t)((s - 8) * 32 + 2 * pkr) * DMODEL + bn;
            r1p = vb + (size_t)((s - 8) * 32 + 2 * pkr + 1) * DMODEL + bn;
        }
        *(float4*)&bA[0] = *(const float4*)r0p; *(float4*)&bA[4] = *(const float4*)(r0p + 4);
        *(float4*)&bB[0] = *(const float4*)r1p; *(float4*)&bB[4] = *(const float4*)(r1p + 4);
    };
    auto loadA = [&](int s) {
        if (s >= 8) {
            const int c0 = (s - 8) * 32;
#pragma unroll
            for (int u = 0; u < 4; ++u)
                raf[u] = *(const float4*)(Abp + (size_t)arow * CH + c0 + kseg + 4 * u);
        }
    };
    auto stage = [&](int bsel, int s) {
        bf16* Ah = (bf16*)(sm + bsel * GSTR);
        bf16* Al = (bf16*)(sm + bsel * GSTR + ABYT);
        bf16* Bh = (bf16*)(sm + bsel * GSTR + 2 * ABYT);
        bf16* Bl = (bf16*)(sm + bsel * GSTR + 2 * ABYT + BBYT);
        uint4 h4, l4;
        if (s < 8) {
            const int db = s * 32 + kseg;
            const float qi = qsm[arow * 17 + (db >> 4)] * 0.25f;
            float p[16];
#pragma unroll
            for (int j = 0; j < 16; ++j) p[j] = qi * qsm[arow * 17 + j];
            split8(p, h4, l4);
            *(uint4*)(Ah + arow * MKS + kseg) = h4;     *(uint4*)(Al + arow * MKS + kseg) = l4;
            split8(p + 8, h4, l4);
            *(uint4*)(Ah + arow * MKS + kseg + 8) = h4; *(uint4*)(Al + arow * MKS + kseg + 8) = l4;
        } else {
            split8((const float*)&raf[0], h4, l4);
            *(uint4*)(Ah + arow * MKS + kseg) = h4;     *(uint4*)(Al + arow * MKS + kseg) = l4;
            split8((const float*)&raf[2], h4, l4);
            *(uint4*)(Ah + arow * MKS + kseg + 8) = h4; *(uint4*)(Al + arow * MKS + kseg + 8) = l4;
        }
        split8(bA, h4, l4);
        *(uint4*)(Bh + (2 * pkr) * KNS + bn) = h4;     *(uint4*)(Bl + (2 * pkr) * KNS + bn) = l4;
        split8(bB, h4, l4);
        *(uint4*)(Bh + (2 * pkr + 1) * KNS + bn) = h4; *(uint4*)(Bl + (2 * pkr + 1) * KNS + bn) = l4;
    };

    loadB(0);
    __syncthreads();            // qsm visible
    stage(0, 0);
    loadB(1);
    __syncthreads();
    for (int s = 0; s < 12; ++s) {
        const unsigned sb = smb + (s & 1) * GSTR;
        mma_stage<false>(sb + offA, sb + ABYT + offA,
                         sb + 2 * ABYT + offB, sb + 2 * ABYT + BBYT + offB, acc);
        if (s + 1 < 12) {
            stage((s + 1) & 1, s + 1);
            if (s + 2 < 12) { loadB(s + 2); loadA(s + 2); }
        }
        __syncthreads();
    }

    float* ob = g_oh + (size_t)(b * LLEN + ch * CH) * DMODEL + h * DVDIM;
#pragma unroll
    for (int mt = 0; mt < 4; ++mt) {
        const int r0 = mbase + mt * 16 + g;
        const float inv0 = 1.f / (dens[r0] + EPS);
        const float inv1 = 1.f / (dens[r0 + 8] + EPS);
#pragma unroll
        for (int nt = 0; nt < 4; ++nt) {
            const int col = nbase + nt * 8 + t * 2;
            const float* a4 = acc[mt * 4 + nt];
            *(float2*)(ob + (size_t)r0 * DMODEL + col)       = make_float2(a4[0] * inv0, a4[1] * inv0);
            *(float2*)(ob + (size_t)(r0 + 8) * DMODEL + col) = make_float2(a4[2] * inv1, a4[3] * inv1);
        }
    }
}

// ---------------- host pipeline ----------------
extern "C" void kernel_launch(void* const* d_in, const int* in_sizes, int n_in,
                              void* d_out, int out_size) {
    (void)in_sizes; (void)n_in; (void)out_size;
    const float* x   = (const float*)d_in[0];
    const float* Wq  = (const float*)d_in[1];
    const float* Wk  = (const float*)d_in[2];
    const float* Wv  = (const float*)d_in[3];
    const float* Wo  = (const float*)d_in[4];
    const float* lqg = (const float*)d_in[5];
    const float* lqb = (const float*)d_in[6];
    const float* lkg = (const float*)d_in[7];
    const float* lkb = (const float*)d_in[8];
    float* out = (float*)d_out;

    const int GEMM_SM = 2 * GSTR;               // 75776
    const int KV_SM   = 2 * KSTR + 8704;        // 78336
    const int AB_SM   = 2 * GSTR + 8704 + 512;  // 84992
    cudaFuncSetAttribute(projqk_kernel, cudaFuncAttributeMaxDynamicSharedMemorySize, GEMM_SM);
    cudaFuncSetAttribute(proj_kernel,   cudaFuncAttributeMaxDynamicSharedMemorySize, GEMM_SM);
    cudaFuncSetAttribute(kvstate_db,    cudaFuncAttributeMaxDynamicSharedMemorySize, KV_SM);
    cudaFuncSetAttribute(attn_b_db,     cudaFuncAttributeMaxDynamicSharedMemorySize, AB_SM);

    float *vp, *ohp;
    cudaGetSymbolAddress((void**)&vp, g_v);
    cudaGetSymbolAddress((void**)&ohp, g_oh);

    projqk_kernel<<<dim3(2, 32, 2), 256, GEMM_SM>>>(x, Wq, Wk);
    proj_kernel<<<dim3(12, 32), 256, GEMM_SM>>>(x, Wv, vp, DMODEL, DMODEL);
    ln_kernel<<<(2 * NTOK) / 8, 256>>>(lqg, lqb, lkg, lkb);
    kvstate_db<<<BB * HH * NC * 2, 256, KV_SM>>>();
    {
        const int total = BB * HH * D2 * DVDIM + BB * HH * D2;
        prefix_kernel<<<(total + 255) / 256, 256>>>();
    }
    attn_a_new<<<BB * HH * NC, 256>>>();
    attn_b_db<<<BB * HH * NC, 256, AB_SM>>>();
    proj_kernel<<<dim3(12, 32), 256, GEMM_SM>>>(ohp, Wo, out, DMODEL, DMODEL);
}